// round 3
// baseline (speedup 1.0000x reference)
#include <cuda_runtime.h>
#include <math.h>

// Problem constants (fixed shapes from setup_inputs)
#define NROWS   131072      // B*H*W = 32*64*64
#define KEMB    512
#define DIM     64
#define THREADS 256
#define BLOCKS  (NROWS / THREADS)   // 512
#define HW      4096                // H*W
#define OUT_ELEMS 8388608LL         // 32*64*64*64
#define REFINE_MARGIN 0.02f

// Scratch (device globals: no allocations allowed)
__device__ unsigned int g_counts[KEMB];
__device__ double g_sumsq;

// ---- packed f32x2 helpers (Blackwell packed fp32 pipe) ----
__device__ __forceinline__ unsigned long long fma2(unsigned long long a,
                                                   unsigned long long b,
                                                   unsigned long long c) {
    unsigned long long d;
    asm("fma.rn.f32x2 %0, %1, %2, %3;" : "=l"(d) : "l"(a), "l"(b), "l"(c));
    return d;
}
__device__ __forceinline__ unsigned long long add2(unsigned long long a,
                                                   unsigned long long b) {
    unsigned long long d;
    asm("add.rn.f32x2 %0, %1, %2;" : "=l"(d) : "l"(a), "l"(b));
    return d;
}

__global__ void vq_zero() {
    int t = threadIdx.x;
    if (t < KEMB) g_counts[t] = 0u;
    if (t == 0)   g_sumsq = 0.0;
}

// Exact (fp64) relative score: ||e||^2 - 2 x.e  (||x||^2 cancels in comparison;
// fp64 error ~1e-14 is far below any gap the fp32 reference could resolve, so
// this reproduces the EXACT argmin regardless of the reference's summation order.)
__device__ __noinline__ double exact_score(const float* __restrict__ x,
                                           const float* __restrict__ e) {
    double dot = 0.0, nrm = 0.0;
    #pragma unroll 8
    for (int d = 0; d < DIM; d++) {
        double xd = (double)x[d], ed = (double)e[d];
        dot = fma(xd, ed, dot);
        nrm = fma(ed, ed, nrm);
    }
    return nrm - 2.0 * dot;
}

extern __shared__ float s_dyn[];

__global__ void __launch_bounds__(THREADS, 1)
vq_main(const float* __restrict__ in,     // [B, C=64, H, W] fp32
        const float* __restrict__ emb,    // [K=512, D=64] fp32
        float* __restrict__ outq,         // [B, C, H, W] fp32
        float* __restrict__ outidx)       // [N] indices as float (nullable)
{
    float* se    = s_dyn;                  // [512*64] codebook
    float* snorm = s_dyn + KEMB * DIM;     // [512]    ||e||^2 (fast-pass only)
    const int tid = threadIdx.x;

    // Cooperative codebook load (128 KB) as float4
    {
        const float4* e4 = reinterpret_cast<const float4*>(emb);
        float4* s4 = reinterpret_cast<float4*>(se);
        #pragma unroll
        for (int i = tid; i < KEMB * DIM / 4; i += THREADS) s4[i] = e4[i];
    }
    __syncthreads();
    for (int k = tid; k < KEMB; k += THREADS) {
        const float* r = se + k * DIM;
        float s = 0.f;
        #pragma unroll
        for (int d = 0; d < DIM; d++) s = fmaf(r[d], r[d], s);
        snorm[k] = s;
    }
    __syncthreads();

    // Row -> input addressing: x[n][c] = in[b*C*HW + c*HW + hw]
    const int row = blockIdx.x * THREADS + tid;
    const int b   = row >> 12;
    const int hw  = row & (HW - 1);
    const float* xin = in + (size_t)b * (DIM * HW) + hw;

    // Load x (coalesced across lanes per c) and pack into f32x2 registers
    unsigned long long xp[DIM / 2];
    #pragma unroll
    for (int i = 0; i < DIM / 2; i++) {
        float2 t;
        t.x = xin[(size_t)(2 * i)     * HW];
        t.y = xin[(size_t)(2 * i + 1) * HW];
        xp[i] = *reinterpret_cast<unsigned long long*>(&t);
    }
    const float* xv = reinterpret_cast<const float*>(xp);  // x[0..63] in order

    // Fast pass: top-2 over K of (||e_k||^2 - 2 x.e_k)  (||x||^2 constant per row)
    float best = 3.4e38f, second = 3.4e38f;
    int   bidx = 0,       sidx = 0;
    #pragma unroll 2
    for (int k = 0; k < KEMB; k++) {
        const ulonglong2* ep = reinterpret_cast<const ulonglong2*>(se + k * DIM);
        unsigned long long a0 = 0ull, a1 = 0ull, a2 = 0ull, a3 = 0ull;
        #pragma unroll
        for (int j = 0; j < 16; j += 2) {
            ulonglong2 e0 = ep[j];        // broadcast LDS.128 (all lanes same k)
            ulonglong2 e1 = ep[j + 1];
            a0 = fma2(xp[2 * j],     e0.x, a0);
            a1 = fma2(xp[2 * j + 1], e0.y, a1);
            a2 = fma2(xp[2 * j + 2], e1.x, a2);
            a3 = fma2(xp[2 * j + 3], e1.y, a3);
        }
        unsigned long long s = add2(add2(a0, a1), add2(a2, a3));
        float2 sf = *reinterpret_cast<float2*>(&s);
        float score = fmaf(-2.0f, sf.x + sf.y, snorm[k]);
        if (score < best) { second = best; sidx = bidx; best = score; bidx = k; }
        else if (score < second) { second = score; sidx = k; }
    }

    // Refinement: if the two leaders are within fp32 rounding reach of each
    // other, re-score both in fp64 (exact). The winner is the true argmin,
    // independent of any backend's fp32 accumulation order. Tie -> lower index
    // (matches argmin first-min semantics).
    if (second - best < REFINE_MARGIN) {
        double d1 = exact_score(xv, se + bidx * DIM);
        double d2 = exact_score(xv, se + sidx * DIM);
        if (d2 < d1 || (d2 == d1 && sidx < bidx)) bidx = sidx;
    }

    atomicAdd(&g_counts[bidx], 1u);

    // Epilogue: straight-through output o = x + (q - x), loss accum (q - x)^2
    float* xout = outq + (size_t)b * (DIM * HW) + hw;
    const float4* q4 = reinterpret_cast<const float4*>(se + bidx * DIM);
    float ssq = 0.f;
    #pragma unroll
    for (int i = 0; i < 16; i++) {
        float4 q = q4[i];
        float x0 = xv[4 * i + 0], x1 = xv[4 * i + 1];
        float x2 = xv[4 * i + 2], x3 = xv[4 * i + 3];
        float d0 = q.x - x0, d1 = q.y - x1, d2 = q.z - x2, d3 = q.w - x3;
        xout[(size_t)(4 * i + 0) * HW] = x0 + d0;
        xout[(size_t)(4 * i + 1) * HW] = x1 + d1;
        xout[(size_t)(4 * i + 2) * HW] = x2 + d2;
        xout[(size_t)(4 * i + 3) * HW] = x3 + d3;
        ssq = fmaf(d0, d0, ssq);
        ssq = fmaf(d1, d1, ssq);
        ssq = fmaf(d2, d2, ssq);
        ssq = fmaf(d3, d3, ssq);
    }
    // warp reduce + one atomic per warp
    #pragma unroll
    for (int off = 16; off > 0; off >>= 1)
        ssq += __shfl_down_sync(0xffffffffu, ssq, off);
    if ((tid & 31) == 0) atomicAdd(&g_sumsq, (double)ssq);

    if (outidx) outidx[row] = (float)bidx;
}

__global__ void vq_fin(float* loss_ptr, float* perp_ptr) {
    __shared__ float red[KEMB];
    const int t = threadIdx.x;
    float p = (float)g_counts[t] * (1.0f / (float)NROWS);
    red[t] = p * logf(p + 1e-10f);
    __syncthreads();
    #pragma unroll
    for (int s = KEMB / 2; s > 0; s >>= 1) {
        if (t < s) red[t] += red[t + s];
        __syncthreads();
    }
    if (t == 0) {
        if (perp_ptr) *perp_ptr = expf(-red[0]);
        if (loss_ptr) *loss_ptr = 0.25f * (float)(g_sumsq / (double)OUT_ELEMS);
    }
}

extern "C" void kernel_launch(void* const* d_in, const int* in_sizes, int n_in,
                              void* d_out, int out_size) {
    const float* in  = (const float*)d_in[0];
    const float* emb = (const float*)d_in[1];
    float* out = (float*)d_out;

    // Output layout: concat of (loss[1], out[8388608], perplexity[1], indices[131072])
    float* lossp = nullptr;
    float* perpp = nullptr;
    float* idxp  = nullptr;
    float* outq  = out;
    if ((long long)out_size == OUT_ELEMS) {
        outq = out;   // only quantized-ST output expected
    } else {
        lossp = out;
        outq  = out + 1;
        perpp = out + 1 + OUT_ELEMS;
        idxp  = perpp + 1;
    }

    const int smem_bytes = (KEMB * DIM + KEMB) * (int)sizeof(float);  // 133120
    cudaFuncSetAttribute(vq_main, cudaFuncAttributeMaxDynamicSharedMemorySize, smem_bytes);

    vq_zero<<<1, KEMB>>>();
    vq_main<<<BLOCKS, THREADS, smem_bytes>>>(in, emb, outq, idxp);
    vq_fin<<<1, KEMB>>>(lossp, perpp);
}

// round 4
// speedup vs baseline: 1.2047x; 1.2047x over previous
#include <cuda_runtime.h>
#include <math.h>

// Problem constants (fixed shapes from setup_inputs)
#define NROWS   131072      // B*H*W = 32*64*64
#define KEMB    512
#define DIM     64
#define THREADS 448         // 14 warps -> 3-4 warps/SMSP (latency hiding)
#define CTAS    148         // persistent: one CTA per SM
#define STRIDE  (CTAS * THREADS)   // 66304 threads; each does <=2 rows
#define HW      4096                // H*W
#define OUT_ELEMS 8388608LL         // 32*64*64*64
#define REFINE_MARGIN 0.02f

// Scratch (device globals: no allocations allowed)
__device__ unsigned int g_counts[KEMB];
__device__ double g_sumsq;

// ---- packed f32x2 helpers (Blackwell packed fp32 pipe) ----
__device__ __forceinline__ unsigned long long fma2(unsigned long long a,
                                                   unsigned long long b,
                                                   unsigned long long c) {
    unsigned long long d;
    asm("fma.rn.f32x2 %0, %1, %2, %3;" : "=l"(d) : "l"(a), "l"(b), "l"(c));
    return d;
}
__device__ __forceinline__ unsigned long long add2(unsigned long long a,
                                                   unsigned long long b) {
    unsigned long long d;
    asm("add.rn.f32x2 %0, %1, %2;" : "=l"(d) : "l"(a), "l"(b));
    return d;
}

__global__ void vq_zero() {
    int t = threadIdx.x;
    if (t < KEMB) g_counts[t] = 0u;
    if (t == 0)   g_sumsq = 0.0;
}

// Exact (fp64) relative score: ||e||^2 - 2 x.e  (||x||^2 cancels in comparison;
// fp64 error ~1e-14 is far below any gap the fp32 reference could resolve, so
// this reproduces the EXACT argmin regardless of the reference's summation order.)
__device__ __noinline__ double exact_score(const float* __restrict__ x,
                                           const float* __restrict__ e) {
    double dot = 0.0, nrm = 0.0;
    #pragma unroll 8
    for (int d = 0; d < DIM; d++) {
        double xd = (double)x[d], ed = (double)e[d];
        dot = fma(xd, ed, dot);
        nrm = fma(ed, ed, nrm);
    }
    return nrm - 2.0 * dot;
}

extern __shared__ float s_dyn[];

__global__ void __launch_bounds__(THREADS, 1)
vq_main(const float* __restrict__ in,     // [B, C=64, H, W] fp32
        const float* __restrict__ emb,    // [K=512, D=64] fp32
        float* __restrict__ outq,         // [B, C, H, W] fp32
        float* __restrict__ outidx)       // [N] indices as float (nullable)
{
    float* se    = s_dyn;                  // [512*64] codebook
    float* snorm = s_dyn + KEMB * DIM;     // [512]    ||e||^2 (fast-pass only)
    const int tid = threadIdx.x;

    // Cooperative codebook load (128 KB) as float4 (once per SM, persistent CTA)
    {
        const float4* e4 = reinterpret_cast<const float4*>(emb);
        float4* s4 = reinterpret_cast<float4*>(se);
        for (int i = tid; i < KEMB * DIM / 4; i += THREADS) s4[i] = e4[i];
    }
    __syncthreads();
    for (int k = tid; k < KEMB; k += THREADS) {
        const float* r = se + k * DIM;
        float s = 0.f;
        #pragma unroll
        for (int d = 0; d < DIM; d++) s = fmaf(r[d], r[d], s);
        snorm[k] = s;
    }
    __syncthreads();

    const int gid = blockIdx.x * THREADS + tid;

    // Each thread handles rows {gid, gid + STRIDE} (second pass ~98% active)
    for (int row = gid; row < NROWS; row += STRIDE) {
        const int b  = row >> 12;
        const int hw = row & (HW - 1);
        const float* xin = in + (size_t)b * (DIM * HW) + hw;

        // Load x (coalesced across lanes per c) packed into f32x2 registers
        unsigned long long xp[DIM / 2];
        #pragma unroll
        for (int i = 0; i < DIM / 2; i++) {
            float2 t;
            t.x = xin[(size_t)(2 * i)     * HW];
            t.y = xin[(size_t)(2 * i + 1) * HW];
            xp[i] = *reinterpret_cast<unsigned long long*>(&t);
        }
        const float* xv = reinterpret_cast<const float*>(xp);

        // Fast pass: top-2 over K of (||e_k||^2 - 2 x.e_k)
        float best = 3.4e38f, second = 3.4e38f;
        int   bidx = 0,       sidx = 0;
        #pragma unroll 2
        for (int k = 0; k < KEMB; k++) {
            const ulonglong2* ep = reinterpret_cast<const ulonglong2*>(se + k * DIM);
            unsigned long long a0 = 0ull, a1 = 0ull, a2 = 0ull, a3 = 0ull;
            #pragma unroll
            for (int j = 0; j < 16; j += 2) {
                ulonglong2 e0 = ep[j];        // broadcast LDS.128
                ulonglong2 e1 = ep[j + 1];
                a0 = fma2(xp[2 * j],     e0.x, a0);
                a1 = fma2(xp[2 * j + 1], e0.y, a1);
                a2 = fma2(xp[2 * j + 2], e1.x, a2);
                a3 = fma2(xp[2 * j + 3], e1.y, a3);
            }
            unsigned long long s = add2(add2(a0, a1), add2(a2, a3));
            float2 sf = *reinterpret_cast<float2*>(&s);
            float score = fmaf(-2.0f, sf.x + sf.y, snorm[k]);
            if (score < best) { second = best; sidx = bidx; best = score; bidx = k; }
            else if (score < second) { second = score; sidx = k; }
        }

        // Near-tie: exact fp64 rescore of the two leaders (tie -> lower index)
        if (second - best < REFINE_MARGIN) {
            double d1 = exact_score(xv, se + bidx * DIM);
            double d2 = exact_score(xv, se + sidx * DIM);
            if (d2 < d1 || (d2 == d1 && sidx < bidx)) bidx = sidx;
        }

        atomicAdd(&g_counts[bidx], 1u);

        // Epilogue: straight-through output o = x + (q - x), loss accum (q - x)^2
        float* xout = outq + (size_t)b * (DIM * HW) + hw;
        const float4* q4 = reinterpret_cast<const float4*>(se + bidx * DIM);
        float ssq = 0.f;
        #pragma unroll
        for (int i = 0; i < 16; i++) {
            float4 q = q4[i];
            float x0 = xv[4 * i + 0], x1 = xv[4 * i + 1];
            float x2 = xv[4 * i + 2], x3 = xv[4 * i + 3];
            float d0 = q.x - x0, d1 = q.y - x1, d2 = q.z - x2, d3 = q.w - x3;
            xout[(size_t)(4 * i + 0) * HW] = x0 + d0;
            xout[(size_t)(4 * i + 1) * HW] = x1 + d1;
            xout[(size_t)(4 * i + 2) * HW] = x2 + d2;
            xout[(size_t)(4 * i + 3) * HW] = x3 + d3;
            ssq = fmaf(d0, d0, ssq);
            ssq = fmaf(d1, d1, ssq);
            ssq = fmaf(d2, d2, ssq);
            ssq = fmaf(d3, d3, ssq);
        }
        // warp reduce + one atomic per warp
        #pragma unroll
        for (int off = 16; off > 0; off >>= 1)
            ssq += __shfl_down_sync(0xffffffffu, ssq, off);
        if ((tid & 31) == 0) atomicAdd(&g_sumsq, (double)ssq);

        if (outidx) outidx[row] = (float)bidx;
    }
}

__global__ void vq_fin(float* loss_ptr, float* perp_ptr) {
    __shared__ float red[KEMB];
    const int t = threadIdx.x;
    float p = (float)g_counts[t] * (1.0f / (float)NROWS);
    red[t] = p * logf(p + 1e-10f);
    __syncthreads();
    #pragma unroll
    for (int s = KEMB / 2; s > 0; s >>= 1) {
        if (t < s) red[t] += red[t + s];
        __syncthreads();
    }
    if (t == 0) {
        if (perp_ptr) *perp_ptr = expf(-red[0]);
        if (loss_ptr) *loss_ptr = 0.25f * (float)(g_sumsq / (double)OUT_ELEMS);
    }
}

extern "C" void kernel_launch(void* const* d_in, const int* in_sizes, int n_in,
                              void* d_out, int out_size) {
    const float* in  = (const float*)d_in[0];
    const float* emb = (const float*)d_in[1];
    float* out = (float*)d_out;

    // Output layout: concat of (loss[1], out[8388608], perplexity[1], indices[131072])
    float* lossp = nullptr;
    float* perpp = nullptr;
    float* idxp  = nullptr;
    float* outq  = out;
    if ((long long)out_size == OUT_ELEMS) {
        outq = out;   // only quantized-ST output expected
    } else {
        lossp = out;
        outq  = out + 1;
        perpp = out + 1 + OUT_ELEMS;
        idxp  = perpp + 1;
    }

    const int smem_bytes = (KEMB * DIM + KEMB) * (int)sizeof(float);  // 133120
    cudaFuncSetAttribute(vq_main, cudaFuncAttributeMaxDynamicSharedMemorySize, smem_bytes);

    vq_zero<<<1, KEMB>>>();
    vq_main<<<CTAS, THREADS, smem_bytes>>>(in, emb, outq, idxp);
    vq_fin<<<1, KEMB>>>(lossp, perpp);
}

// round 6
// speedup vs baseline: 1.5578x; 1.2932x over previous
#include <cuda_runtime.h>
#include <cuda_bf16.h>
#include <math.h>
#include <cstdint>

// Problem constants
#define NROWS   131072
#define KEMB    512
#define DIM     64
#define HW      4096
#define OUT_ELEMS 8388608LL
#define REFINE_MARGIN 0.02f

#define TILE_M  256
#define NTILES  (NROWS / TILE_M)     // 512
#define CTAS    148
#define THREADS 256
#define XS_STRIDE 68                 // fp32 elems per row (pad: 68%32=4 bank shift)

// smem layout (bytes)
#define OFF_BFRAG  0                 // 64*4*2*32 uint2 = 131072
#define OFF_XS     131072            // 256*68*4 = 69632
#define OFF_SNORM  200704            // 512*4
#define OFF_MB     202752            // 256*4
#define OFF_MS     203776
#define OFF_MBI    204800
#define OFF_MSI    205824
#define SMEM_TOTAL 206848

__device__ unsigned int g_counts[KEMB];
__device__ double g_sumsq;

__global__ void vq_zero() {
    int t = threadIdx.x;
    if (t < KEMB) g_counts[t] = 0u;
    if (t == 0)   g_sumsq = 0.0;
}

// Exact fp64 relative score (argmin-equivalent): ||e||^2 - 2 x.e
__device__ __forceinline__ double exact_score(const float* x, const float* __restrict__ e) {
    double dot = 0.0, nrm = 0.0;
    #pragma unroll
    for (int d = 0; d < DIM; d++) {
        double xd = (double)x[d], ed = (double)e[d];
        dot = fma(xd, ed, dot);
        nrm = fma(ed, ed, nrm);
    }
    return nrm - 2.0 * dot;
}

// hi/lo bf16 split of two floats, packed into b32 (low 16 = first elem)
__device__ __forceinline__ void cvt2(float a, float b, uint32_t& h, uint32_t& l) {
    __nv_bfloat16 ha = __float2bfloat16_rn(a), hb = __float2bfloat16_rn(b);
    float la = a - __bfloat162float(ha), lb = b - __bfloat162float(hb);
    __nv_bfloat16 la1 = __float2bfloat16_rn(la), lb1 = __float2bfloat16_rn(lb);
    h = (uint32_t)__bfloat16_as_ushort(ha) | ((uint32_t)__bfloat16_as_ushort(hb) << 16);
    l = (uint32_t)__bfloat16_as_ushort(la1) | ((uint32_t)__bfloat16_as_ushort(lb1) << 16);
}

// m16n8k16 bf16 MMA (baseline PTX, compiles at compute_103)
__device__ __forceinline__ void mma16816(float* c, const uint32_t* a, uint32_t b0, uint32_t b1) {
    asm volatile(
        "mma.sync.aligned.m16n8k16.row.col.f32.bf16.bf16.f32 "
        "{%0,%1,%2,%3}, {%4,%5,%6,%7}, {%8,%9}, {%0,%1,%2,%3};"
        : "+f"(c[0]), "+f"(c[1]), "+f"(c[2]), "+f"(c[3])
        : "r"(a[0]), "r"(a[1]), "r"(a[2]), "r"(a[3]), "r"(b0), "r"(b1));
}

// top-2 update (strict <: earlier/lower candidate wins ties)
#define T2_UPD(bst, bi_, sec, si_, sc, kk) do { \
    if ((sc) < (bst)) { (sec) = (bst); (si_) = (bi_); (bst) = (sc); (bi_) = (kk); } \
    else if ((sc) < (sec)) { (sec) = (sc); (si_) = (kk); } } while (0)

// merge other top-2 (ob,obi,os,osi) into mine; self wins ties
#define T2_MERGE(b, bi, s, si, ob, obi, os, osi) do { \
    if ((ob) < (b)) { \
        float nb = (ob); int nbi = (obi); \
        float ns; int nsi; \
        if ((b) < (os)) { ns = (b); nsi = (bi); } else { ns = (os); nsi = (osi); } \
        (b) = nb; (bi) = nbi; (s) = ns; (si) = nsi; \
    } else { \
        if ((ob) < (s)) { (s) = (ob); (si) = (obi); } \
    } } while (0)

extern __shared__ char s_raw[];

__global__ void __launch_bounds__(THREADS, 1)
vq_main(const float* __restrict__ in, const float* __restrict__ emb,
        float* __restrict__ outq, float* __restrict__ outidx)
{
    char* sm = s_raw;
    uint2* bfrag = reinterpret_cast<uint2*>(sm + OFF_BFRAG);
    float* xs    = reinterpret_cast<float*>(sm + OFF_XS);
    float* snorm = reinterpret_cast<float*>(sm + OFF_SNORM);
    float* mb    = reinterpret_cast<float*>(sm + OFF_MB);
    float* ms    = reinterpret_cast<float*>(sm + OFF_MS);
    int*   mbi   = reinterpret_cast<int*>(sm + OFF_MBI);
    int*   msi   = reinterpret_cast<int*>(sm + OFF_MSI);

    const int tid = threadIdx.x;
    const int wid = tid >> 5, lane = tid & 31;
    const int lq = lane >> 2, lr = lane & 3;

    // ---- One-time: pack codebook into B fragments (hi/lo), compute ||e||^2 ----
    for (int i = tid; i < 64 * 4 * 2 * 32; i += THREADS) {
        int ln = i & 31, split = (i >> 5) & 1, ks = (i >> 6) & 3, ns = i >> 8;
        int n = ns * 8 + (ln >> 2);
        int k0 = ks * 16 + (ln & 3) * 2;
        const float* er = emb + n * DIM + k0;
        uint32_t h0, l0, h1, l1;
        cvt2(er[0], er[1], h0, l0);
        cvt2(er[8], er[9], h1, l1);
        bfrag[i] = split == 0 ? make_uint2(h0, h1) : make_uint2(l0, l1);
    }
    for (int k = tid; k < KEMB; k += THREADS) {
        const float* r = emb + k * DIM;
        float s = 0.f;
        #pragma unroll
        for (int d = 0; d < DIM; d++) s = fmaf(r[d], r[d], s);
        snorm[k] = s;
    }

    for (int t = blockIdx.x; t < NTILES; t += CTAS) {
        __syncthreads();   // previous epilogue done; safe to overwrite xs/top2

        // ---- stage x tile: xs[r][c] = in[(b*64+c)*HW + hw0 + r] ----
        const int b   = t >> 4;               // 16 tiles per image
        const int hw0 = (t & 15) * TILE_M;
        {
            const float4* base4 = reinterpret_cast<const float4*>(
                in + (size_t)b * (DIM * HW) + hw0);
            #pragma unroll
            for (int p = 0; p < 16; p++) {
                int idx = tid + p * THREADS;           // 4096 float4
                int c = idx >> 6, q = idx & 63;
                float4 v = base4[c * (HW / 4) + q];
                xs[(4 * q + 0) * XS_STRIDE + c] = v.x;
                xs[(4 * q + 1) * XS_STRIDE + c] = v.y;
                xs[(4 * q + 2) * XS_STRIDE + c] = v.z;
                xs[(4 * q + 3) * XS_STRIDE + c] = v.w;
            }
        }
        __syncthreads();

        // ---- build A fragments (hi/lo) in registers: 2 row-groups x 4 ksteps ----
        uint32_t ahi[2][4][4], alo[2][4][4];
        #pragma unroll
        for (int rg = 0; rg < 2; rg++) {
            const int rl = wid * 32 + rg * 16 + lq;
            #pragma unroll
            for (int ks = 0; ks < 4; ks++) {
                const int c0 = ks * 16 + lr * 2;
                const float* p00 = xs + rl * XS_STRIDE + c0;
                const float* p10 = xs + (rl + 8) * XS_STRIDE + c0;
                cvt2(p00[0], p00[1], ahi[rg][ks][0], alo[rg][ks][0]);
                cvt2(p10[0], p10[1], ahi[rg][ks][1], alo[rg][ks][1]);
                cvt2(p00[8], p00[9], ahi[rg][ks][2], alo[rg][ks][2]);
                cvt2(p10[8], p10[9], ahi[rg][ks][3], alo[rg][ks][3]);
            }
        }

        // ---- main loop over 64 n-steps (8 codes each) ----
        float tb[2][2], ts[2][2];   // [rg][lo/hi row] best/second
        int   tbi[2][2], tsi[2][2];
        #pragma unroll
        for (int rg = 0; rg < 2; rg++)
            #pragma unroll
            for (int hh = 0; hh < 2; hh++) {
                tb[rg][hh] = 3.4e38f; ts[rg][hh] = 3.4e38f;
                tbi[rg][hh] = 0; tsi[rg][hh] = 0;
            }

        #pragma unroll 4
        for (int ns = 0; ns < 64; ns++) {
            float acc[2][4] = {{0.f, 0.f, 0.f, 0.f}, {0.f, 0.f, 0.f, 0.f}};
            #pragma unroll
            for (int ks = 0; ks < 4; ks++) {
                uint2 bh = bfrag[((ns * 4 + ks) * 2 + 0) * 32 + lane];
                uint2 bl = bfrag[((ns * 4 + ks) * 2 + 1) * 32 + lane];
                #pragma unroll
                for (int rg = 0; rg < 2; rg++) {
                    mma16816(acc[rg], ahi[rg][ks], bh.x, bh.y);
                    mma16816(acc[rg], ahi[rg][ks], bl.x, bl.y);
                    mma16816(acc[rg], alo[rg][ks], bh.x, bh.y);
                }
            }
            const int ka = ns * 8 + lr * 2;
            float2 nv = *reinterpret_cast<const float2*>(snorm + ka);
            #pragma unroll
            for (int rg = 0; rg < 2; rg++) {
                float s0 = fmaf(-2.f, acc[rg][0], nv.x);
                float s1 = fmaf(-2.f, acc[rg][1], nv.y);
                float s2 = fmaf(-2.f, acc[rg][2], nv.x);
                float s3 = fmaf(-2.f, acc[rg][3], nv.y);
                T2_UPD(tb[rg][0], tbi[rg][0], ts[rg][0], tsi[rg][0], s0, ka);
                T2_UPD(tb[rg][0], tbi[rg][0], ts[rg][0], tsi[rg][0], s1, ka + 1);
                T2_UPD(tb[rg][1], tbi[rg][1], ts[rg][1], tsi[rg][1], s2, ka);
                T2_UPD(tb[rg][1], tbi[rg][1], ts[rg][1], tsi[rg][1], s3, ka + 1);
            }
        }

        // ---- merge across the 4 lanes sharing each row (xor 1, xor 2) ----
        #pragma unroll
        for (int rg = 0; rg < 2; rg++)
            #pragma unroll
            for (int hh = 0; hh < 2; hh++) {
                float b_ = tb[rg][hh], s_ = ts[rg][hh];
                int bi_ = tbi[rg][hh], si_ = tsi[rg][hh];
                #pragma unroll
                for (int off = 1; off <= 2; off <<= 1) {
                    float ob  = __shfl_xor_sync(0xffffffffu, b_, off);
                    float os  = __shfl_xor_sync(0xffffffffu, s_, off);
                    int   obi = __shfl_xor_sync(0xffffffffu, bi_, off);
                    int   osi = __shfl_xor_sync(0xffffffffu, si_, off);
                    T2_MERGE(b_, bi_, s_, si_, ob, obi, os, osi);
                }
                if (lr == 0) {
                    int row = wid * 32 + rg * 16 + hh * 8 + lq;
                    mb[row] = b_; ms[row] = s_; mbi[row] = bi_; msi[row] = si_;
                }
            }
        __syncthreads();

        // ---- epilogue: one thread per row (256 threads = 256 rows) ----
        {
            const int r = tid;
            float fb = mb[r], fs = ms[r];
            int fbi = mbi[r], fsi = msi[r];

            const int rowg = t * TILE_M + r;
            const int bb   = rowg >> 12;
            const int hw   = rowg & (HW - 1);
            const float* xin = in + (size_t)bb * (DIM * HW) + hw;

            float x[DIM];
            #pragma unroll
            for (int d = 0; d < DIM; d++) x[d] = xin[(size_t)d * HW];

            if (fs - fb < REFINE_MARGIN) {
                double d1 = exact_score(x, emb + fbi * DIM);
                double d2 = exact_score(x, emb + fsi * DIM);
                if (d2 < d1 || (d2 == d1 && fsi < fbi)) fbi = fsi;
            }

            atomicAdd(&g_counts[fbi], 1u);

            float* xout = outq + (size_t)bb * (DIM * HW) + hw;
            const float4* q4 = reinterpret_cast<const float4*>(emb + fbi * DIM);
            float ssq = 0.f;
            #pragma unroll
            for (int i = 0; i < 16; i++) {
                float4 q = q4[i];
                float d0 = q.x - x[4 * i + 0], d1 = q.y - x[4 * i + 1];
                float d2 = q.z - x[4 * i + 2], d3 = q.w - x[4 * i + 3];
                xout[(size_t)(4 * i + 0) * HW] = x[4 * i + 0] + d0;
                xout[(size_t)(4 * i + 1) * HW] = x[4 * i + 1] + d1;
                xout[(size_t)(4 * i + 2) * HW] = x[4 * i + 2] + d2;
                xout[(size_t)(4 * i + 3) * HW] = x[4 * i + 3] + d3;
                ssq = fmaf(d0, d0, ssq); ssq = fmaf(d1, d1, ssq);
                ssq = fmaf(d2, d2, ssq); ssq = fmaf(d3, d3, ssq);
            }
            #pragma unroll
            for (int off = 16; off > 0; off >>= 1)
                ssq += __shfl_down_sync(0xffffffffu, ssq, off);
            if (lane == 0) atomicAdd(&g_sumsq, (double)ssq);

            if (outidx) outidx[rowg] = (float)fbi;
        }
    }
}

__global__ void vq_fin(float* loss_ptr, float* perp_ptr) {
    __shared__ float red[KEMB];
    const int t = threadIdx.x;
    float p = (float)g_counts[t] * (1.0f / (float)NROWS);
    red[t] = p * logf(p + 1e-10f);
    __syncthreads();
    #pragma unroll
    for (int s = KEMB / 2; s > 0; s >>= 1) {
        if (t < s) red[t] += red[t + s];
        __syncthreads();
    }
    if (t == 0) {
        if (perp_ptr) *perp_ptr = expf(-red[0]);
        if (loss_ptr) *loss_ptr = 0.25f * (float)(g_sumsq / (double)OUT_ELEMS);
    }
}

extern "C" void kernel_launch(void* const* d_in, const int* in_sizes, int n_in,
                              void* d_out, int out_size) {
    const float* in  = (const float*)d_in[0];
    const float* emb = (const float*)d_in[1];
    float* out = (float*)d_out;

    float* lossp = nullptr; float* perpp = nullptr; float* idxp = nullptr;
    float* outq = out;
    if ((long long)out_size == OUT_ELEMS) {
        outq = out;
    } else {
        lossp = out;
        outq  = out + 1;
        perpp = out + 1 + OUT_ELEMS;
        idxp  = perpp + 1;
    }

    cudaFuncSetAttribute(vq_main, cudaFuncAttributeMaxDynamicSharedMemorySize, SMEM_TOTAL);

    vq_zero<<<1, KEMB>>>();
    vq_main<<<CTAS, THREADS, SMEM_TOTAL>>>(in, emb, outq, idxp);
    vq_fin<<<1, KEMB>>>(lossp, perpp);
}

// round 7
// speedup vs baseline: 2.9704x; 1.9068x over previous
#include <cuda_runtime.h>
#include <cuda_fp16.h>
#include <math.h>
#include <cstdint>

#define NROWS   131072
#define KEMB    512
#define DIM     64
#define HW      4096
#define OUT_ELEMS 8388608LL
#define TILE_M  128
#define NTILES  (NROWS / TILE_M)     // 1024
#define CTAS    148
#define THREADS 256
#define XS_STRIDE 68
#define SCORE_BIAS 512.0f
#define REFINE_MARGIN 0.35f

// smem offsets (bytes)
#define OFF_BFRAG 0                  // 64*4*32*8 = 65536
#define OFF_XS    65536              // 128*68*4 = 34816
#define OFF_NVB   100352             // 512*4 biased norms (fp32 + 512)
#define OFF_NRMH  102400             // 512*4 compensated norm hi
#define OFF_NRML  104448             // 512*4 compensated norm lo
#define OFF_T3    106496             // 3*128*4
#define OFF_BIDX  108032             // 128*4
#define OFF_CNT   108544             // 512*4
#define SMEM_TOTAL 110592

__device__ unsigned int g_counts[KEMB];
__device__ double g_sumsq;

// fp16 m16n8k16 MMA (baseline PTX, OK at compute_103)
__device__ __forceinline__ void mma16816h(float* c, const uint32_t* a, uint32_t b0, uint32_t b1) {
    asm volatile(
        "mma.sync.aligned.m16n8k16.row.col.f32.f16.f16.f32 "
        "{%0,%1,%2,%3}, {%4,%5,%6,%7}, {%8,%9}, {%0,%1,%2,%3};"
        : "+f"(c[0]), "+f"(c[1]), "+f"(c[2]), "+f"(c[3])
        : "r"(a[0]), "r"(a[1]), "r"(a[2]), "r"(a[3]), "r"(b0), "r"(b1));
}

__device__ __forceinline__ uint32_t packh2(float a, float b) {
    __half2 h = __floats2half2_rn(a, b);
    return *reinterpret_cast<uint32_t*>(&h);
}

// branchless sorted top-3 insert (packed u32: score-bits | idx)
#define T3_UPD(b1, b2, b3, v) do { \
    uint32_t _t1 = max(b1, v); b1 = min(b1, v); \
    uint32_t _t2 = max(b2, _t1); b2 = min(b2, _t1); \
    b3 = min(b3, _t2); } while (0)

// merge sorted triple (o1<=o2<=o3) into (b1<=b2<=b3)
#define T3_MERGE(b1, b2, b3, o1, o2, o3) do { \
    uint32_t _c1 = min(b1, o1), _d1 = max(b1, o1); \
    uint32_t _c2 = min(b2, o2), _d2 = max(b2, o2); \
    uint32_t _c3 = min(b3, o3); \
    b1 = _c1; \
    uint32_t _r2 = min(_d1, _c2), _t1 = max(_d1, _c2); \
    uint32_t _t2 = min(_d2, _c3); \
    b2 = _r2; b3 = min(_t1, _t2); } while (0)

// compensated fp32 dot of x[64] (smem) with e row (gmem); near-exact (~1e-13)
__device__ __forceinline__ void comp_dot(const float* __restrict__ x,
                                         const float* __restrict__ e,
                                         float& s_out, float& c_out) {
    float s = 0.f, c = 0.f;
    #pragma unroll
    for (int d = 0; d < DIM; d++) {
        float p  = __fmul_rn(x[d], e[d]);
        float ep = fmaf(x[d], e[d], -p);
        float z  = __fadd_rn(s, p);
        float bv = __fsub_rn(z, s);
        float err = __fadd_rn(__fsub_rn(s, __fsub_rn(z, bv)), __fsub_rn(p, bv));
        s = z;
        c = __fadd_rn(c, __fadd_rn(err, ep));
    }
    s_out = s; c_out = c;
}

extern __shared__ char s_raw[];

__global__ void __launch_bounds__(THREADS, 1)
vq_main(const float* __restrict__ in, const float* __restrict__ emb,
        float* __restrict__ outq, float* __restrict__ outidx)
{
    char* sm = s_raw;
    uint2* bfrag = reinterpret_cast<uint2*>(sm + OFF_BFRAG);
    float* xs    = reinterpret_cast<float*>(sm + OFF_XS);
    float* nvb   = reinterpret_cast<float*>(sm + OFF_NVB);
    float* nrmh  = reinterpret_cast<float*>(sm + OFF_NRMH);
    float* nrml  = reinterpret_cast<float*>(sm + OFF_NRML);
    uint32_t* t3 = reinterpret_cast<uint32_t*>(sm + OFF_T3);     // [3][128]
    int* sbidx   = reinterpret_cast<int*>(sm + OFF_BIDX);
    unsigned int* scnt = reinterpret_cast<unsigned int*>(sm + OFF_CNT);

    const int tid = threadIdx.x;
    const int wid = tid >> 5, lane = tid & 31;
    const int lq = lane >> 2, lr = lane & 3;

    // ---- one-time: B fragments (fp16), compensated norms, biased norms ----
    for (int i = tid; i < 64 * 4 * 32; i += THREADS) {
        int ln = i & 31, ks = (i >> 5) & 3, ns = i >> 7;
        int n  = ns * 8 + (ln >> 2);
        int k0 = ks * 16 + (ln & 3) * 2;
        const float* er = emb + n * DIM + k0;
        bfrag[i] = make_uint2(packh2(er[0], er[1]), packh2(er[8], er[9]));
    }
    for (int k = tid; k < KEMB; k += THREADS) {
        const float* e = emb + k * DIM;
        float s = 0.f, c = 0.f;
        #pragma unroll
        for (int d = 0; d < DIM; d++) {
            float p  = __fmul_rn(e[d], e[d]);
            float ep = fmaf(e[d], e[d], -p);
            float z  = __fadd_rn(s, p);
            float bv = __fsub_rn(z, s);
            float err = __fadd_rn(__fsub_rn(s, __fsub_rn(z, bv)), __fsub_rn(p, bv));
            s = z;
            c = __fadd_rn(c, __fadd_rn(err, ep));
        }
        nrmh[k] = s; nrml[k] = c;
        nvb[k]  = s + SCORE_BIAS;
    }
    for (int i = tid; i < KEMB; i += THREADS) scnt[i] = 0u;

    for (int t = blockIdx.x; t < NTILES; t += CTAS) {
        __syncthreads();   // xs / t3 safe to overwrite

        // ---- stage x tile: xs[r][c] = in[(b*64+c)*HW + hw0 + r] ----
        const int b   = t >> 5;               // 32 tiles per image
        const int hw0 = (t & 31) * TILE_M;
        {
            const float4* base4 = reinterpret_cast<const float4*>(
                in + (size_t)b * (DIM * HW) + hw0);
            #pragma unroll
            for (int p = 0; p < 8; p++) {
                int idx = tid + p * THREADS;   // 2048 float4
                int c = idx >> 5, q = idx & 31;
                float4 v = base4[c * (HW / 4) + q];
                xs[(4 * q + 0) * XS_STRIDE + c] = v.x;
                xs[(4 * q + 1) * XS_STRIDE + c] = v.y;
                xs[(4 * q + 2) * XS_STRIDE + c] = v.z;
                xs[(4 * q + 3) * XS_STRIDE + c] = v.w;
            }
        }
        __syncthreads();

        // ---- A fragments (fp16), rows wid*16 + {lq, lq+8} ----
        uint32_t a[4][4];
        {
            const int rl = wid * 16 + lq;
            #pragma unroll
            for (int ks = 0; ks < 4; ks++) {
                const int c0 = ks * 16 + lr * 2;
                const float* p0 = xs + rl * XS_STRIDE + c0;
                const float* p1 = xs + (rl + 8) * XS_STRIDE + c0;
                a[ks][0] = packh2(p0[0], p0[1]);
                a[ks][1] = packh2(p1[0], p1[1]);
                a[ks][2] = packh2(p0[8], p0[9]);
                a[ks][3] = packh2(p1[8], p1[9]);
            }
        }

        // ---- main loop: 64 n-steps x 8 codes ----
        uint32_t b1a = 0xFFFFFFFFu, b2a = 0xFFFFFFFFu, b3a = 0xFFFFFFFFu;  // row lq
        uint32_t b1b = 0xFFFFFFFFu, b2b = 0xFFFFFFFFu, b3b = 0xFFFFFFFFu;  // row lq+8
        #pragma unroll 4
        for (int ns = 0; ns < 64; ns++) {
            float acc01[4] = {0.f, 0.f, 0.f, 0.f};
            float acc23[4] = {0.f, 0.f, 0.f, 0.f};
            uint2 bf0 = bfrag[(ns * 4 + 0) * 32 + lane];
            uint2 bf1 = bfrag[(ns * 4 + 1) * 32 + lane];
            uint2 bf2 = bfrag[(ns * 4 + 2) * 32 + lane];
            uint2 bf3 = bfrag[(ns * 4 + 3) * 32 + lane];
            mma16816h(acc01, a[0], bf0.x, bf0.y);
            mma16816h(acc23, a[2], bf2.x, bf2.y);
            mma16816h(acc01, a[1], bf1.x, bf1.y);
            mma16816h(acc23, a[3], bf3.x, bf3.y);

            const int ka = ns * 8 + lr * 2;
            float2 nv = *reinterpret_cast<const float2*>(nvb + ka);
            float s0 = fmaf(-2.f, acc01[0] + acc23[0], nv.x);
            float s1 = fmaf(-2.f, acc01[1] + acc23[1], nv.y);
            float s2 = fmaf(-2.f, acc01[2] + acc23[2], nv.x);
            float s3 = fmaf(-2.f, acc01[3] + acc23[3], nv.y);
            uint32_t u0 = (__float_as_uint(s0) & 0xFFFFFE00u) | (uint32_t)ka;
            uint32_t u1 = (__float_as_uint(s1) & 0xFFFFFE00u) | (uint32_t)(ka + 1);
            uint32_t u2 = (__float_as_uint(s2) & 0xFFFFFE00u) | (uint32_t)ka;
            uint32_t u3 = (__float_as_uint(s3) & 0xFFFFFE00u) | (uint32_t)(ka + 1);
            T3_UPD(b1a, b2a, b3a, u0);
            T3_UPD(b1a, b2a, b3a, u1);
            T3_UPD(b1b, b2b, b3b, u2);
            T3_UPD(b1b, b2b, b3b, u3);
        }

        // ---- merge across the 4 lanes (lr) sharing each row ----
        #pragma unroll
        for (int off = 1; off <= 2; off <<= 1) {
            uint32_t o1 = __shfl_xor_sync(0xffffffffu, b1a, off);
            uint32_t o2 = __shfl_xor_sync(0xffffffffu, b2a, off);
            uint32_t o3 = __shfl_xor_sync(0xffffffffu, b3a, off);
            T3_MERGE(b1a, b2a, b3a, o1, o2, o3);
            o1 = __shfl_xor_sync(0xffffffffu, b1b, off);
            o2 = __shfl_xor_sync(0xffffffffu, b2b, off);
            o3 = __shfl_xor_sync(0xffffffffu, b3b, off);
            T3_MERGE(b1b, b2b, b3b, o1, o2, o3);
        }
        if (lr == 0) {
            int ra = wid * 16 + lq, rb = ra + 8;
            t3[ra] = b1a; t3[128 + ra] = b2a; t3[256 + ra] = b3a;
            t3[rb] = b1b; t3[128 + rb] = b2b; t3[256 + rb] = b3b;
        }
        __syncthreads();

        // ---- phase A: select + refine (one thread per row) ----
        if (tid < TILE_M) {
            const int r = tid;
            uint32_t u1 = t3[r], u2 = t3[128 + r], u3 = t3[256 + r];
            float s1f = __uint_as_float(u1 & 0xFFFFFE00u);
            float s2f = __uint_as_float(u2 & 0xFFFFFE00u);
            int i1 = (int)(u1 & 511u), i2 = (int)(u2 & 511u), i3 = (int)(u3 & 511u);
            int fbi = i1;
            if (s2f - s1f < REFINE_MARGIN) {
                const float* xrow = xs + r * XS_STRIDE;
                int   cand[3] = {i1, i2, i3};
                double bestd = 1e300; int besti = 0x7fffffff;
                #pragma unroll
                for (int c = 0; c < 3; c++) {
                    int k = cand[c];
                    float ds, dc;
                    comp_dot(xrow, emb + k * DIM, ds, dc);
                    double d = ((double)nrmh[k] + (double)nrml[k])
                             - 2.0 * ((double)ds + (double)dc);
                    if (d < bestd || (d == bestd && k < besti)) { bestd = d; besti = k; }
                }
                fbi = besti;
            }
            sbidx[r] = fbi;
            atomicAdd(&scnt[fbi], 1u);
            if (outidx) outidx[t * TILE_M + r] = (float)fbi;
        }
        __syncthreads();

        // ---- phase B: outputs + loss (two threads per row, 32 channels each) ----
        {
            const int r = tid & 127, h = tid >> 7;
            const int fbi = sbidx[r];
            const int rowg = t * TILE_M + r;
            const int bb = rowg >> 12, hw = rowg & (HW - 1);
            float* xout = outq + (size_t)bb * (DIM * HW) + hw + (size_t)(h * 32) * HW;
            const float4* q4 = reinterpret_cast<const float4*>(emb + fbi * DIM + h * 32);
            const float4* x4 = reinterpret_cast<const float4*>(xs + r * XS_STRIDE + h * 32);
            float ssq = 0.f;
            #pragma unroll
            for (int i = 0; i < 8; i++) {
                float4 q = q4[i];
                float4 x = x4[i];
                float d0 = q.x - x.x, d1 = q.y - x.y, d2 = q.z - x.z, d3 = q.w - x.w;
                xout[(size_t)(4 * i + 0) * HW] = x.x + d0;
                xout[(size_t)(4 * i + 1) * HW] = x.y + d1;
                xout[(size_t)(4 * i + 2) * HW] = x.z + d2;
                xout[(size_t)(4 * i + 3) * HW] = x.w + d3;
                ssq = fmaf(d0, d0, ssq); ssq = fmaf(d1, d1, ssq);
                ssq = fmaf(d2, d2, ssq); ssq = fmaf(d3, d3, ssq);
            }
            #pragma unroll
            for (int off = 16; off > 0; off >>= 1)
                ssq += __shfl_down_sync(0xffffffffu, ssq, off);
            if (lane == 0) atomicAdd(&g_sumsq, (double)ssq);
        }
    }

    // flush per-CTA histogram
    __syncthreads();
    for (int i = tid; i < KEMB; i += THREADS)
        if (scnt[i]) atomicAdd(&g_counts[i], scnt[i]);
}

// fin: compute loss/perplexity, then reset globals for the next (graph) call
__global__ void vq_fin(float* loss_ptr, float* perp_ptr) {
    __shared__ float red[KEMB];
    const int t = threadIdx.x;
    float p = (float)g_counts[t] * (1.0f / (float)NROWS);
    red[t] = p * logf(p + 1e-10f);
    __syncthreads();
    #pragma unroll
    for (int s = KEMB / 2; s > 0; s >>= 1) {
        if (t < s) red[t] += red[t + s];
        __syncthreads();
    }
    if (t == 0) {
        if (perp_ptr) *perp_ptr = expf(-red[0]);
        if (loss_ptr) *loss_ptr = 0.25f * (float)(g_sumsq / (double)OUT_ELEMS);
        g_sumsq = 0.0;
    }
    g_counts[t] = 0u;   // reset for next call (initial state is zero too)
}

__global__ void vq_nop() {}

extern "C" void kernel_launch(void* const* d_in, const int* in_sizes, int n_in,
                              void* d_out, int out_size) {
    const float* in  = (const float*)d_in[0];
    const float* emb = (const float*)d_in[1];
    float* out = (float*)d_out;

    float* lossp = nullptr; float* perpp = nullptr; float* idxp = nullptr;
    float* outq = out;
    if ((long long)out_size == OUT_ELEMS) {
        outq = out;
    } else {
        lossp = out;
        outq  = out + 1;
        perpp = out + 1 + OUT_ELEMS;
        idxp  = perpp + 1;
    }

    cudaFuncSetAttribute(vq_main, cudaFuncAttributeMaxDynamicSharedMemorySize, SMEM_TOTAL);

    vq_main<<<CTAS, THREADS, SMEM_TOTAL>>>(in, emb, outq, idxp);
    vq_fin<<<1, KEMB>>>(lossp, perpp);
    vq_nop<<<1, 32>>>();
}

// round 8
// speedup vs baseline: 2.9861x; 1.0053x over previous
#include <cuda_runtime.h>
#include <cuda_fp16.h>
#include <math.h>
#include <cstdint>

#define NROWS   131072
#define KEMB    512
#define DIM     64
#define HW      4096
#define OUT_ELEMS 8388608LL
#define TILE_M  128
#define NTILES  (NROWS / TILE_M)     // 1024
#define CTAS    148
#define THREADS 512
#define XS_STRIDE 68
#define SCORE_BIAS 512.0f
#define REFINE_MARGIN 0.35f

// smem offsets (bytes)
#define OFF_BFRAG 0                  // 64*2*32 uint4 = 65536
#define OFF_XS    65536              // 128*68*4 = 34816
#define OFF_NVB   100352             // 512*4
#define OFF_NRMH  102400             // 512*4
#define OFF_NRML  104448             // 512*4
#define OFF_T3    106496             // 6*128*4 = 3072 (two halves x sorted triple)
#define OFF_BIDX  109568             // 128*4
#define OFF_CNT   110080             // 512*4
#define SMEM_TOTAL 112128

__device__ unsigned int g_counts[KEMB];
__device__ double g_sumsq;

__device__ __forceinline__ void mma16816h(float* c, const uint32_t* a, uint32_t b0, uint32_t b1) {
    asm volatile(
        "mma.sync.aligned.m16n8k16.row.col.f32.f16.f16.f32 "
        "{%0,%1,%2,%3}, {%4,%5,%6,%7}, {%8,%9}, {%0,%1,%2,%3};"
        : "+f"(c[0]), "+f"(c[1]), "+f"(c[2]), "+f"(c[3])
        : "r"(a[0]), "r"(a[1]), "r"(a[2]), "r"(a[3]), "r"(b0), "r"(b1));
}

__device__ __forceinline__ uint32_t packh2(float a, float b) {
    __half2 h = __floats2half2_rn(a, b);
    return *reinterpret_cast<uint32_t*>(&h);
}

// branchless sorted top-3 insert (packed u32: score-bits | idx; min = better)
#define T3_UPD(b1, b2, b3, v) do { \
    uint32_t _t1 = max(b1, v); b1 = min(b1, v); \
    uint32_t _t2 = max(b2, _t1); b2 = min(b2, _t1); \
    b3 = min(b3, _t2); } while (0)

// merge sorted triple (o1<=o2<=o3) into sorted (b1<=b2<=b3)
#define T3_MERGE(b1, b2, b3, o1, o2, o3) do { \
    uint32_t _c1 = min(b1, o1), _d1 = max(b1, o1); \
    uint32_t _c2 = min(b2, o2), _d2 = max(b2, o2); \
    uint32_t _c3 = min(b3, o3); \
    b1 = _c1; \
    uint32_t _r2 = min(_d1, _c2), _t1 = max(_d1, _c2); \
    uint32_t _t2 = min(_d2, _c3); \
    b2 = _r2; b3 = min(_t1, _t2); } while (0)

// compensated fp32 dot (near-exact ~1e-13)
__device__ __forceinline__ void comp_dot(const float* __restrict__ x,
                                         const float* __restrict__ e,
                                         float& s_out, float& c_out) {
    float s = 0.f, c = 0.f;
    #pragma unroll
    for (int d = 0; d < DIM; d++) {
        float p  = __fmul_rn(x[d], e[d]);
        float ep = fmaf(x[d], e[d], -p);
        float z  = __fadd_rn(s, p);
        float bv = __fsub_rn(z, s);
        float err = __fadd_rn(__fsub_rn(s, __fsub_rn(z, bv)), __fsub_rn(p, bv));
        s = z;
        c = __fadd_rn(c, __fadd_rn(err, ep));
    }
    s_out = s; c_out = c;
}

extern __shared__ char s_raw[];

__global__ void __launch_bounds__(THREADS, 1)
vq_main(const float* __restrict__ in, const float* __restrict__ emb,
        float* __restrict__ outq, float* __restrict__ outidx)
{
    char* sm = s_raw;
    uint4* bfrag = reinterpret_cast<uint4*>(sm + OFF_BFRAG);
    float* xs    = reinterpret_cast<float*>(sm + OFF_XS);
    float* nvb   = reinterpret_cast<float*>(sm + OFF_NVB);
    float* nrmh  = reinterpret_cast<float*>(sm + OFF_NRMH);
    float* nrml  = reinterpret_cast<float*>(sm + OFF_NRML);
    uint32_t* t3 = reinterpret_cast<uint32_t*>(sm + OFF_T3);     // [6][128]
    int* sbidx   = reinterpret_cast<int*>(sm + OFF_BIDX);
    unsigned int* scnt = reinterpret_cast<unsigned int*>(sm + OFF_CNT);

    const int tid = threadIdx.x;
    const int wid = tid >> 5, lane = tid & 31;
    const int lq = lane >> 2, lr = lane & 3;
    const int rg = wid >> 1;            // row-group 0..7 (16 rows each)
    const int nh = wid & 1;             // codebook half 0..1

    // ---- one-time: B fragments (uint4 = ks-pair), norms ----
    for (int i = tid; i < 64 * 2 * 32; i += THREADS) {
        int ln = i & 31, kp = (i >> 5) & 1, ns = i >> 6;
        int n  = ns * 8 + (ln >> 2);
        int k0 = kp * 32 + (ln & 3) * 2;        // ks = 2kp -> k base
        const float* er = emb + n * DIM;
        bfrag[i] = make_uint4(
            packh2(er[k0],      er[k0 + 1]),
            packh2(er[k0 + 8],  er[k0 + 9]),
            packh2(er[k0 + 16], er[k0 + 17]),
            packh2(er[k0 + 24], er[k0 + 25]));
    }
    for (int k = tid; k < KEMB; k += THREADS) {
        const float* e = emb + k * DIM;
        float s = 0.f, c = 0.f;
        #pragma unroll
        for (int d = 0; d < DIM; d++) {
            float p  = __fmul_rn(e[d], e[d]);
            float ep = fmaf(e[d], e[d], -p);
            float z  = __fadd_rn(s, p);
            float bv = __fsub_rn(z, s);
            float err = __fadd_rn(__fsub_rn(s, __fsub_rn(z, bv)), __fsub_rn(p, bv));
            s = z;
            c = __fadd_rn(c, __fadd_rn(err, ep));
        }
        nrmh[k] = s; nrml[k] = c;
        nvb[k]  = s + SCORE_BIAS;
    }
    for (int i = tid; i < KEMB; i += THREADS) scnt[i] = 0u;

    for (int t = blockIdx.x; t < NTILES; t += CTAS) {
        __syncthreads();

        // ---- stage x tile: xs[r][c] = in[(b*64+c)*HW + hw0 + r] ----
        const int b   = t >> 5;
        const int hw0 = (t & 31) * TILE_M;
        {
            const float4* base4 = reinterpret_cast<const float4*>(
                in + (size_t)b * (DIM * HW) + hw0);
            #pragma unroll
            for (int p = 0; p < 4; p++) {
                int idx = tid + p * THREADS;   // 2048 float4
                int c = idx >> 5, q = idx & 31;
                float4 v = base4[c * (HW / 4) + q];
                xs[(4 * q + 0) * XS_STRIDE + c] = v.x;
                xs[(4 * q + 1) * XS_STRIDE + c] = v.y;
                xs[(4 * q + 2) * XS_STRIDE + c] = v.z;
                xs[(4 * q + 3) * XS_STRIDE + c] = v.w;
            }
        }
        __syncthreads();

        // ---- A fragments (fp16), rows rg*16 + {lq, lq+8} ----
        uint32_t a[4][4];
        {
            const int rl = rg * 16 + lq;
            #pragma unroll
            for (int ks = 0; ks < 4; ks++) {
                const int c0 = ks * 16 + lr * 2;
                const float* p0 = xs + rl * XS_STRIDE + c0;
                const float* p1 = xs + (rl + 8) * XS_STRIDE + c0;
                a[ks][0] = packh2(p0[0], p0[1]);
                a[ks][1] = packh2(p1[0], p1[1]);
                a[ks][2] = packh2(p0[8], p0[9]);
                a[ks][3] = packh2(p1[8], p1[9]);
            }
        }

        // ---- main loop: this warp's 32 n-steps (codebook half nh) ----
        uint32_t b1a = 0xFFFFFFFFu, b2a = 0xFFFFFFFFu, b3a = 0xFFFFFFFFu;
        uint32_t b1b = 0xFFFFFFFFu, b2b = 0xFFFFFFFFu, b3b = 0xFFFFFFFFu;
        const int ns0 = nh * 32;
        #pragma unroll 2
        for (int nsi = 0; nsi < 32; nsi++) {
            const int ns = ns0 + nsi;
            uint4 bA = bfrag[(ns * 2 + 0) * 32 + lane];   // ks0, ks1
            uint4 bB = bfrag[(ns * 2 + 1) * 32 + lane];   // ks2, ks3
            float acc01[4] = {0.f, 0.f, 0.f, 0.f};
            float acc23[4] = {0.f, 0.f, 0.f, 0.f};
            mma16816h(acc01, a[0], bA.x, bA.y);
            mma16816h(acc23, a[2], bB.x, bB.y);
            mma16816h(acc01, a[1], bA.z, bA.w);
            mma16816h(acc23, a[3], bB.z, bB.w);

            const int ka = ns * 8 + lr * 2;
            float2 nv = *reinterpret_cast<const float2*>(nvb + ka);
            float s0 = fmaf(-2.f, acc01[0] + acc23[0], nv.x);
            float s1 = fmaf(-2.f, acc01[1] + acc23[1], nv.y);
            float s2 = fmaf(-2.f, acc01[2] + acc23[2], nv.x);
            float s3 = fmaf(-2.f, acc01[3] + acc23[3], nv.y);
            uint32_t u0 = (__float_as_uint(s0) & 0xFFFFFE00u) | (uint32_t)ka;
            uint32_t u1 = (__float_as_uint(s1) & 0xFFFFFE00u) | (uint32_t)(ka + 1);
            uint32_t u2 = (__float_as_uint(s2) & 0xFFFFFE00u) | (uint32_t)ka;
            uint32_t u3 = (__float_as_uint(s3) & 0xFFFFFE00u) | (uint32_t)(ka + 1);
            T3_UPD(b1a, b2a, b3a, u0);
            T3_UPD(b1a, b2a, b3a, u1);
            T3_UPD(b1b, b2b, b3b, u2);
            T3_UPD(b1b, b2b, b3b, u3);
        }

        // ---- merge across the 4 lanes (lr) sharing each row ----
        #pragma unroll
        for (int off = 1; off <= 2; off <<= 1) {
            uint32_t o1 = __shfl_xor_sync(0xffffffffu, b1a, off);
            uint32_t o2 = __shfl_xor_sync(0xffffffffu, b2a, off);
            uint32_t o3 = __shfl_xor_sync(0xffffffffu, b3a, off);
            T3_MERGE(b1a, b2a, b3a, o1, o2, o3);
            o1 = __shfl_xor_sync(0xffffffffu, b1b, off);
            o2 = __shfl_xor_sync(0xffffffffu, b2b, off);
            o3 = __shfl_xor_sync(0xffffffffu, b3b, off);
            T3_MERGE(b1b, b2b, b3b, o1, o2, o3);
        }
        if (lr == 0) {
            int ra = rg * 16 + lq, rb = ra + 8;
            t3[(nh * 3 + 0) * 128 + ra] = b1a;
            t3[(nh * 3 + 1) * 128 + ra] = b2a;
            t3[(nh * 3 + 2) * 128 + ra] = b3a;
            t3[(nh * 3 + 0) * 128 + rb] = b1b;
            t3[(nh * 3 + 1) * 128 + rb] = b2b;
            t3[(nh * 3 + 2) * 128 + rb] = b3b;
        }
        __syncthreads();

        // ---- phase A: merge halves + select + refine (one thread per row) ----
        if (tid < TILE_M) {
            const int r = tid;
            uint32_t u1 = t3[0 * 128 + r], u2 = t3[1 * 128 + r], u3 = t3[2 * 128 + r];
            uint32_t o1 = t3[3 * 128 + r], o2 = t3[4 * 128 + r], o3 = t3[5 * 128 + r];
            T3_MERGE(u1, u2, u3, o1, o2, o3);
            float s1f = __uint_as_float(u1 & 0xFFFFFE00u);
            float s2f = __uint_as_float(u2 & 0xFFFFFE00u);
            int i1 = (int)(u1 & 511u), i2 = (int)(u2 & 511u), i3 = (int)(u3 & 511u);
            int fbi = i1;
            if (s2f - s1f < REFINE_MARGIN) {
                const float* xrow = xs + r * XS_STRIDE;
                int   cand[3] = {i1, i2, i3};
                double bestd = 1e300; int besti = 0x7fffffff;
                #pragma unroll
                for (int c = 0; c < 3; c++) {
                    int k = cand[c];
                    float ds, dc;
                    comp_dot(xrow, emb + k * DIM, ds, dc);
                    double d = ((double)nrmh[k] + (double)nrml[k])
                             - 2.0 * ((double)ds + (double)dc);
                    if (d < bestd || (d == bestd && k < besti)) { bestd = d; besti = k; }
                }
                fbi = besti;
            }
            sbidx[r] = fbi;
            atomicAdd(&scnt[fbi], 1u);
            if (outidx) outidx[t * TILE_M + r] = (float)fbi;
        }
        __syncthreads();

        // ---- phase B: outputs + loss (four threads per row, 16 channels each) ----
        {
            const int r = tid & 127, h = tid >> 7;
            const int fbi = sbidx[r];
            const int rowg = t * TILE_M + r;
            const int bb = rowg >> 12, hw = rowg & (HW - 1);
            float* xout = outq + (size_t)bb * (DIM * HW) + hw + (size_t)(h * 16) * HW;
            const float4* q4 = reinterpret_cast<const float4*>(emb + fbi * DIM + h * 16);
            const float4* x4 = reinterpret_cast<const float4*>(xs + r * XS_STRIDE + h * 16);
            float ssq = 0.f;
            #pragma unroll
            for (int i = 0; i < 4; i++) {
                float4 q = q4[i];
                float4 x = x4[i];
                float d0 = q.x - x.x, d1 = q.y - x.y, d2 = q.z - x.z, d3 = q.w - x.w;
                xout[(size_t)(4 * i + 0) * HW] = x.x + d0;
                xout[(size_t)(4 * i + 1) * HW] = x.y + d1;
                xout[(size_t)(4 * i + 2) * HW] = x.z + d2;
                xout[(size_t)(4 * i + 3) * HW] = x.w + d3;
                ssq = fmaf(d0, d0, ssq); ssq = fmaf(d1, d1, ssq);
                ssq = fmaf(d2, d2, ssq); ssq = fmaf(d3, d3, ssq);
            }
            #pragma unroll
            for (int off = 16; off > 0; off >>= 1)
                ssq += __shfl_down_sync(0xffffffffu, ssq, off);
            if (lane == 0) atomicAdd(&g_sumsq, (double)ssq);
        }
    }

    // flush per-CTA histogram
    __syncthreads();
    for (int i = tid; i < KEMB; i += THREADS)
        if (scnt[i]) atomicAdd(&g_counts[i], scnt[i]);
}

// fin: compute loss/perplexity, then reset globals for the next (graph) call
__global__ void vq_fin(float* loss_ptr, float* perp_ptr) {
    __shared__ float red[KEMB];
    const int t = threadIdx.x;
    float p = (float)g_counts[t] * (1.0f / (float)NROWS);
    red[t] = p * logf(p + 1e-10f);
    __syncthreads();
    #pragma unroll
    for (int s = KEMB / 2; s > 0; s >>= 1) {
        if (t < s) red[t] += red[t + s];
        __syncthreads();
    }
    if (t == 0) {
        if (perp_ptr) *perp_ptr = expf(-red[0]);
        if (loss_ptr) *loss_ptr = 0.25f * (float)(g_sumsq / (double)OUT_ELEMS);
        g_sumsq = 0.0;
    }
    g_counts[t] = 0u;
}

__global__ void vq_nop() {}

extern "C" void kernel_launch(void* const* d_in, const int* in_sizes, int n_in,
                              void* d_out, int out_size) {
    const float* in  = (const float*)d_in[0];
    const float* emb = (const float*)d_in[1];
    float* out = (float*)d_out;

    float* lossp = nullptr; float* perpp = nullptr; float* idxp = nullptr;
    float* outq = out;
    if ((long long)out_size == OUT_ELEMS) {
        outq = out;
    } else {
        lossp = out;
        outq  = out + 1;
        perpp = out + 1 + OUT_ELEMS;
        idxp  = perpp + 1;
    }

    cudaFuncSetAttribute(vq_main, cudaFuncAttributeMaxDynamicSharedMemorySize, SMEM_TOTAL);

    vq_main<<<CTAS, THREADS, SMEM_TOTAL>>>(in, emb, outq, idxp);
    vq_fin<<<1, KEMB>>>(lossp, perpp);
    vq_nop<<<1, 32>>>();
}

// round 9
// speedup vs baseline: 3.9385x; 1.3189x over previous
#include <cuda_runtime.h>
#include <cuda_fp16.h>
#include <math.h>
#include <cstdint>

#define NROWS   131072
#define KEMB    512
#define DIM     64
#define HW      4096
#define OUT_ELEMS 8388608LL
#define TILE_M  128
#define NTILES  (NROWS / TILE_M)     // 1024
#define CTAS    148
#define THREADS 512
#define XS_R    132                  // channel-major row stride (floats), conflict-free
#define XS_BUF_F (DIM * XS_R)        // 8448 floats = 33792 B
#define SCORE_BIAS 512.0f
#define REFINE_MARGIN 0.35f

// smem offsets (bytes)
#define OFF_BFRAG 0                  // 64*2*32 uint4 = 65536
#define OFF_XS    65536              // 3 * 33792 = 101376
#define OFF_NVB   166912             // 512*4
#define OFF_NRMH  168960             // 512*4
#define OFF_NRML  171008             // 512*4
#define OFF_T3    173056             // 2 * 6*128*4 = 6144
#define OFF_CNT   179200             // 512*4
#define SMEM_TOTAL 181248

__device__ unsigned int g_counts[KEMB];
__device__ double g_sumsq;

__device__ __forceinline__ void mma16816h(float* c, const uint32_t* a, uint32_t b0, uint32_t b1) {
    asm volatile(
        "mma.sync.aligned.m16n8k16.row.col.f32.f16.f16.f32 "
        "{%0,%1,%2,%3}, {%4,%5,%6,%7}, {%8,%9}, {%0,%1,%2,%3};"
        : "+f"(c[0]), "+f"(c[1]), "+f"(c[2]), "+f"(c[3])
        : "r"(a[0]), "r"(a[1]), "r"(a[2]), "r"(a[3]), "r"(b0), "r"(b1));
}

__device__ __forceinline__ uint32_t packh2(float a, float b) {
    __half2 h = __floats2half2_rn(a, b);
    return *reinterpret_cast<uint32_t*>(&h);
}

__device__ __forceinline__ uint32_t smem_u32(const void* p) {
    uint32_t a;
    asm("{ .reg .u64 t; cvta.to.shared.u64 t, %1; cvt.u32.u64 %0, t; }" : "=r"(a) : "l"(p));
    return a;
}

// branchless sorted top-3 insert (packed u32: score-bits | idx; min = better)
#define T3_UPD(b1, b2, b3, v) do { \
    uint32_t _t1 = max(b1, v); b1 = min(b1, v); \
    uint32_t _t2 = max(b2, _t1); b2 = min(b2, _t1); \
    b3 = min(b3, _t2); } while (0)

// merge sorted triple (o1<=o2<=o3) into sorted (b1<=b2<=b3)
#define T3_MERGE(b1, b2, b3, o1, o2, o3) do { \
    uint32_t _c1 = min(b1, o1), _d1 = max(b1, o1); \
    uint32_t _c2 = min(b2, o2), _d2 = max(b2, o2); \
    uint32_t _c3 = min(b3, o3); \
    b1 = _c1; \
    uint32_t _r2 = min(_d1, _c2), _t1 = max(_d1, _c2); \
    uint32_t _t2 = min(_d2, _c3); \
    b2 = _r2; b3 = min(_t1, _t2); } while (0)

// compensated fp32 dot, x strided by XS_R (near-exact ~1e-13)
__device__ __forceinline__ void comp_dot_s(const float* __restrict__ xp,
                                           const float* __restrict__ e,
                                           float& s_out, float& c_out) {
    float s = 0.f, c = 0.f;
    #pragma unroll
    for (int d = 0; d < DIM; d++) {
        float xd = xp[d * XS_R];
        float p  = __fmul_rn(xd, e[d]);
        float ep = fmaf(xd, e[d], -p);
        float z  = __fadd_rn(s, p);
        float bv = __fsub_rn(z, s);
        float err = __fadd_rn(__fsub_rn(s, __fsub_rn(z, bv)), __fsub_rn(p, bv));
        s = z;
        c = __fadd_rn(c, __fadd_rn(err, ep));
    }
    s_out = s; c_out = c;
}

extern __shared__ char s_raw[];

// cp.async stage of one tile (channel-major): xs[c*XS_R + 4q] <- in[... c*HW + hw0 + 4q]
__device__ __forceinline__ void stage_async(const float* __restrict__ gbase,
                                            uint32_t smem_dst, int tid) {
    #pragma unroll
    for (int p = 0; p < 4; p++) {
        int idx = tid + p * THREADS;        // 2048 chunks of 16B
        int c = idx >> 5, q = idx & 31;
        uint32_t s = smem_dst + (uint32_t)(c * XS_R + 4 * q) * 4u;
        const float* g = gbase + (size_t)c * HW + 4 * q;
        asm volatile("cp.async.cg.shared.global [%0], [%1], 16;" :: "r"(s), "l"(g) : "memory");
    }
    asm volatile("cp.async.commit_group;" ::: "memory");
}

__global__ void __launch_bounds__(THREADS, 1)
vq_main(const float* __restrict__ in, const float* __restrict__ emb,
        float* __restrict__ outq, float* __restrict__ outidx)
{
    char* sm = s_raw;
    uint4* bfrag = reinterpret_cast<uint4*>(sm + OFF_BFRAG);
    float* xsall = reinterpret_cast<float*>(sm + OFF_XS);
    float* nvb   = reinterpret_cast<float*>(sm + OFF_NVB);
    float* nrmh  = reinterpret_cast<float*>(sm + OFF_NRMH);
    float* nrml  = reinterpret_cast<float*>(sm + OFF_NRML);
    uint32_t* t3 = reinterpret_cast<uint32_t*>(sm + OFF_T3);     // [2][6][128]
    unsigned int* scnt = reinterpret_cast<unsigned int*>(sm + OFF_CNT);
    const uint32_t smb_xs = smem_u32(sm + OFF_XS);

    const int tid = threadIdx.x;
    const int wid = tid >> 5, lane = tid & 31;
    const int lq = lane >> 2, lr = lane & 3;
    const int rg = wid >> 1;            // row-group 0..7
    const int nh = wid & 1;             // codebook half

    // ---- one-time: B fragments, norms, counts ----
    for (int i = tid; i < 64 * 2 * 32; i += THREADS) {
        int ln = i & 31, kp = (i >> 5) & 1, ns = i >> 6;
        int n  = ns * 8 + (ln >> 2);
        int k0 = kp * 32 + (ln & 3) * 2;
        const float* er = emb + n * DIM;
        bfrag[i] = make_uint4(
            packh2(er[k0],      er[k0 + 1]),
            packh2(er[k0 + 8],  er[k0 + 9]),
            packh2(er[k0 + 16], er[k0 + 17]),
            packh2(er[k0 + 24], er[k0 + 25]));
    }
    for (int k = tid; k < KEMB; k += THREADS) {
        const float* e = emb + k * DIM;
        float s = 0.f, c = 0.f;
        #pragma unroll
        for (int d = 0; d < DIM; d++) {
            float p  = __fmul_rn(e[d], e[d]);
            float ep = fmaf(e[d], e[d], -p);
            float z  = __fadd_rn(s, p);
            float bv = __fsub_rn(z, s);
            float err = __fadd_rn(__fsub_rn(s, __fsub_rn(z, bv)), __fsub_rn(p, bv));
            s = z;
            c = __fadd_rn(c, __fadd_rn(err, ep));
        }
        nrmh[k] = s; nrml[k] = c;
        nvb[k]  = s + SCORE_BIAS;
    }
    for (int i = tid; i < KEMB; i += THREADS) scnt[i] = 0u;

    // ---- prologue: stage first tile into buf 0 ----
    const int t0 = blockIdx.x;
    {
        const int b = t0 >> 5, hw0 = (t0 & 31) * TILE_M;
        stage_async(in + (size_t)b * (DIM * HW) + hw0, smb_xs, tid);
        asm volatile("cp.async.wait_all;" ::: "memory");
    }
    __syncthreads();

    int it = 0;
    for (int t = t0; t < NTILES; t += CTAS, it++) {
        const int cb = it - (it / 3) * 3;            // it % 3
        const float* xc = xsall + cb * XS_BUF_F;
        const int par = it & 1;

        // ---- A fragments from channel-major xs ----
        uint32_t a[4][4];
        {
            const int rl = rg * 16 + lq;
            #pragma unroll
            for (int ks = 0; ks < 4; ks++) {
                const int c0 = ks * 16 + lr * 2;
                const float* b0 = xc + c0 * XS_R;
                a[ks][0] = packh2(b0[rl],              b0[XS_R + rl]);
                a[ks][1] = packh2(b0[rl + 8],          b0[XS_R + rl + 8]);
                a[ks][2] = packh2(b0[8 * XS_R + rl],     b0[9 * XS_R + rl]);
                a[ks][3] = packh2(b0[8 * XS_R + rl + 8], b0[9 * XS_R + rl + 8]);
            }
        }

        // ---- prefetch next tile (hidden under mainloop) ----
        const int tn = t + CTAS;
        if (tn < NTILES) {
            const int nb = (it + 1) - ((it + 1) / 3) * 3;
            const int b = tn >> 5, hw0 = (tn & 31) * TILE_M;
            stage_async(in + (size_t)b * (DIM * HW) + hw0,
                        smb_xs + (uint32_t)nb * 33792u, tid);
        }

        // ---- main loop: this warp's 32 n-steps (codebook half nh) ----
        uint32_t b1a = 0xFFFFFFFFu, b2a = 0xFFFFFFFFu, b3a = 0xFFFFFFFFu;
        uint32_t b1b = 0xFFFFFFFFu, b2b = 0xFFFFFFFFu, b3b = 0xFFFFFFFFu;
        const int ns0 = nh * 32;
        #pragma unroll 2
        for (int nsi = 0; nsi < 32; nsi++) {
            const int ns = ns0 + nsi;
            uint4 bA = bfrag[(ns * 2 + 0) * 32 + lane];
            uint4 bB = bfrag[(ns * 2 + 1) * 32 + lane];
            float acc01[4] = {0.f, 0.f, 0.f, 0.f};
            float acc23[4] = {0.f, 0.f, 0.f, 0.f};
            mma16816h(acc01, a[0], bA.x, bA.y);
            mma16816h(acc23, a[2], bB.x, bB.y);
            mma16816h(acc01, a[1], bA.z, bA.w);
            mma16816h(acc23, a[3], bB.z, bB.w);

            const int ka = ns * 8 + lr * 2;
            float2 nv = *reinterpret_cast<const float2*>(nvb + ka);
            float s0 = fmaf(-2.f, acc01[0] + acc23[0], nv.x);
            float s1 = fmaf(-2.f, acc01[1] + acc23[1], nv.y);
            float s2 = fmaf(-2.f, acc01[2] + acc23[2], nv.x);
            float s3 = fmaf(-2.f, acc01[3] + acc23[3], nv.y);
            uint32_t u0 = (__float_as_uint(s0) & 0xFFFFFE00u) | (uint32_t)ka;
            uint32_t u1 = (__float_as_uint(s1) & 0xFFFFFE00u) | (uint32_t)(ka + 1);
            uint32_t u2 = (__float_as_uint(s2) & 0xFFFFFE00u) | (uint32_t)ka;
            uint32_t u3 = (__float_as_uint(s3) & 0xFFFFFE00u) | (uint32_t)(ka + 1);
            T3_UPD(b1a, b2a, b3a, u0);
            T3_UPD(b1a, b2a, b3a, u1);
            T3_UPD(b1b, b2b, b3b, u2);
            T3_UPD(b1b, b2b, b3b, u3);
        }

        // ---- merge across 4 lanes sharing each row; write t3[par] ----
        #pragma unroll
        for (int off = 1; off <= 2; off <<= 1) {
            uint32_t o1 = __shfl_xor_sync(0xffffffffu, b1a, off);
            uint32_t o2 = __shfl_xor_sync(0xffffffffu, b2a, off);
            uint32_t o3 = __shfl_xor_sync(0xffffffffu, b3a, off);
            T3_MERGE(b1a, b2a, b3a, o1, o2, o3);
            o1 = __shfl_xor_sync(0xffffffffu, b1b, off);
            o2 = __shfl_xor_sync(0xffffffffu, b2b, off);
            o3 = __shfl_xor_sync(0xffffffffu, b3b, off);
            T3_MERGE(b1b, b2b, b3b, o1, o2, o3);
        }
        if (lr == 0) {
            uint32_t* tp = t3 + par * 768;
            int ra = rg * 16 + lq, rb = ra + 8;
            tp[(nh * 3 + 0) * 128 + ra] = b1a;
            tp[(nh * 3 + 1) * 128 + ra] = b2a;
            tp[(nh * 3 + 2) * 128 + ra] = b3a;
            tp[(nh * 3 + 0) * 128 + rb] = b1b;
            tp[(nh * 3 + 1) * 128 + rb] = b2b;
            tp[(nh * 3 + 2) * 128 + rb] = b3b;
        }

        asm volatile("cp.async.wait_all;" ::: "memory");
        __syncthreads();   // t3[par] visible; next xs buffer complete

        // ---- fused epilogue (tid<128); other warps race into next tile ----
        if (tid < TILE_M) {
            const int r = tid;
            const uint32_t* tp = t3 + par * 768;
            uint32_t u1 = tp[r],       u2 = tp[128 + r], u3 = tp[256 + r];
            uint32_t o1 = tp[384 + r], o2 = tp[512 + r], o3 = tp[640 + r];
            T3_MERGE(u1, u2, u3, o1, o2, o3);
            float s1f = __uint_as_float(u1 & 0xFFFFFE00u);
            float s2f = __uint_as_float(u2 & 0xFFFFFE00u);
            int i1 = (int)(u1 & 511u), i2 = (int)(u2 & 511u), i3 = (int)(u3 & 511u);
            int fbi = i1;
            if (s2f - s1f < REFINE_MARGIN) {
                const float* xp = xc + r;
                int cand[3] = {i1, i2, i3};
                double bestd = 1e300; int besti = 0x7fffffff;
                #pragma unroll
                for (int c = 0; c < 3; c++) {
                    int k = cand[c];
                    float ds, dc;
                    comp_dot_s(xp, emb + k * DIM, ds, dc);
                    double d = ((double)nrmh[k] + (double)nrml[k])
                             - 2.0 * ((double)ds + (double)dc);
                    if (d < bestd || (d == bestd && k < besti)) { bestd = d; besti = k; }
                }
                fbi = besti;
            }
            atomicAdd(&scnt[fbi], 1u);

            const int rowg = t * TILE_M + r;
            const int bb = rowg >> 12, hw = rowg & (HW - 1);
            if (outidx) outidx[rowg] = (float)fbi;

            float* xout = outq + (size_t)bb * (DIM * HW) + hw;
            const float4* q4 = reinterpret_cast<const float4*>(emb + fbi * DIM);
            const float* xcol = xc + r;
            float ssq = 0.f;
            #pragma unroll
            for (int i = 0; i < 16; i++) {
                float4 q = q4[i];
                float x0 = xcol[(4 * i + 0) * XS_R];
                float x1 = xcol[(4 * i + 1) * XS_R];
                float x2 = xcol[(4 * i + 2) * XS_R];
                float x3 = xcol[(4 * i + 3) * XS_R];
                float d0 = q.x - x0, d1 = q.y - x1, d2 = q.z - x2, d3 = q.w - x3;
                xout[(size_t)(4 * i + 0) * HW] = x0 + d0;
                xout[(size_t)(4 * i + 1) * HW] = x1 + d1;
                xout[(size_t)(4 * i + 2) * HW] = x2 + d2;
                xout[(size_t)(4 * i + 3) * HW] = x3 + d3;
                ssq = fmaf(d0, d0, ssq); ssq = fmaf(d1, d1, ssq);
                ssq = fmaf(d2, d2, ssq); ssq = fmaf(d3, d3, ssq);
            }
            #pragma unroll
            for (int off = 16; off > 0; off >>= 1)
                ssq += __shfl_down_sync(0xffffffffu, ssq, off);
            if (lane == 0) atomicAdd(&g_sumsq, (double)ssq);
        }
    }

    // flush per-CTA histogram
    __syncthreads();
    for (int i = tid; i < KEMB; i += THREADS)
        if (scnt[i]) atomicAdd(&g_counts[i], scnt[i]);
}

// fin: compute loss/perplexity, then reset globals for the next (graph) call
__global__ void vq_fin(float* loss_ptr, float* perp_ptr) {
    __shared__ float red[KEMB];
    const int t = threadIdx.x;
    float p = (float)g_counts[t] * (1.0f / (float)NROWS);
    red[t] = p * logf(p + 1e-10f);
    __syncthreads();
    #pragma unroll
    for (int s = KEMB / 2; s > 0; s >>= 1) {
        if (t < s) red[t] += red[t + s];
        __syncthreads();
    }
    if (t == 0) {
        if (perp_ptr) *perp_ptr = expf(-red[0]);
        if (loss_ptr) *loss_ptr = 0.25f * (float)(g_sumsq / (double)OUT_ELEMS);
        g_sumsq = 0.0;
    }
    g_counts[t] = 0u;
}

__global__ void vq_nop() {}

extern "C" void kernel_launch(void* const* d_in, const int* in_sizes, int n_in,
                              void* d_out, int out_size) {
    const float* in  = (const float*)d_in[0];
    const float* emb = (const float*)d_in[1];
    float* out = (float*)d_out;

    float* lossp = nullptr; float* perpp = nullptr; float* idxp = nullptr;
    float* outq = out;
    if ((long long)out_size == OUT_ELEMS) {
        outq = out;
    } else {
        lossp = out;
        outq  = out + 1;
        perpp = out + 1 + OUT_ELEMS;
        idxp  = perpp + 1;
    }

    cudaFuncSetAttribute(vq_main, cudaFuncAttributeMaxDynamicSharedMemorySize, SMEM_TOTAL);

    vq_main<<<CTAS, THREADS, SMEM_TOTAL>>>(in, emb, outq, idxp);
    vq_fin<<<1, KEMB>>>(lossp, perpp);
    vq_nop<<<1, 32>>>();
}